// round 7
// baseline (speedup 1.0000x reference)
#include <cuda_runtime.h>
#include <cstdint>

// RoIAlign, warp-cooperative + batched loads for MLP.
// One warp = (roi n, ph, 16-channel group). Lane = pw(7) x sx(2) x corner(2)
// = 28 active lanes; each lane owns one x-corner column with a combined
// (wx*wy) weight. Channels processed in 2 batches of 8: all 32 LDGs of a
// batch are issued before any consumption (MLP ~32), then FMA + shuffle
// reduce + coalesced store.
//
// features: (B=2, C=256, H=200, W=200) f32 NCHW
// rois:     (N, 5) f32  [batch_idx, x1, y1, x2, y2]
// out:      (N, 256, 7, 7) f32
// SPATIAL_SCALE = 1/16, SAMPLING_RATIO = 2, POOLED = 7x7

#define POOLED 7
#define SCALE  0.0625f
#define CH     256
#define FH     200
#define FW     200
#define CPW    16              // channels per warp
#define NCG    (CH / CPW)      // 16 channel groups
#define CB     8               // channels per load batch
#define PLANE  (FH * FW)

__global__ __launch_bounds__(256)
void roi_align_warp(const float* __restrict__ features,
                    const float* __restrict__ rois,
                    float* __restrict__ out)
{
    const int lane = threadIdx.x & 31;
    const int wid  = blockIdx.x * (blockDim.x >> 5) + (threadIdx.x >> 5);

    // wid = (n*NCG + cg)*7 + ph  (ph fastest: consecutive warps share rows in L1)
    const int ph = wid % POOLED;
    const int t  = wid / POOLED;
    const int cg = t % NCG;
    const int n  = t / NCG;

    // ---- per-ROI scalars (uniform across warp) ----
    const float* roi = rois + n * 5;
    const int   b  = (int)__ldg(&roi[0]);
    const float x1 = __ldg(&roi[1]) * SCALE;
    const float y1 = __ldg(&roi[2]) * SCALE;
    const float x2 = __ldg(&roi[3]) * SCALE;
    const float y2 = __ldg(&roi[4]) * SCALE;

    const float bin_w = fmaxf(x2 - x1, 1.0f) * (1.0f / POOLED);
    const float bin_h = fmaxf(y2 - y1, 1.0f) * (1.0f / POOLED);

    // ---- lane's x-corner column + weight (computed once) ----
    const int pw     = min(lane >> 2, POOLED - 1);  // lanes 28-31 duplicate pw=6
    const int sx     = (lane >> 1) & 1;
    const int corner = lane & 1;

    float wx;
    int   xc;
    {
        const float x  = fmaf((float)pw + 0.25f + 0.5f * (float)sx, bin_w, x1);
        const bool  vx = (x >= -1.0f) && (x <= (float)FW);
        const float cx = fmaxf(x, 0.0f);
        const int   lo = min((int)floorf(cx), FW - 1);
        const int   hi = min(lo + 1, FW - 1);
        const float fx = (lo >= FW - 1) ? 0.0f : (cx - (float)lo);
        xc = corner ? hi : lo;
        wx = corner ? fx : (1.0f - fx);
        if (!vx) wx = 0.0f;
    }

    // ---- y interpolation for the 2 samples of this ph (uniform) ----
    int   yrow[4];
    float wy[4];
#pragma unroll
    for (int sy = 0; sy < 2; sy++) {
        const float y  = fmaf((float)ph + 0.25f + 0.5f * (float)sy, bin_h, y1);
        const bool  vy = (y >= -1.0f) && (y <= (float)FH);
        const float cy = fmaxf(y, 0.0f);
        const int   lo = min((int)floorf(cy), FH - 1);
        const int   hi = min(lo + 1, FH - 1);
        const float fy = (lo >= FH - 1) ? 0.0f : (cy - (float)lo);
        yrow[2 * sy]     = lo;
        yrow[2 * sy + 1] = hi;
        wy[2 * sy]       = vy ? (1.0f - fy) : 0.0f;
        wy[2 * sy + 1]   = vy ? fy          : 0.0f;
    }

    // Combined per-lane tap weights (x * y), premultiplied by mean factor 1/4.
    const float w0 = 0.25f * wx * wy[0];
    const float w1 = 0.25f * wx * wy[1];
    const float w2 = 0.25f * wx * wy[2];
    const float w3 = 0.25f * wx * wy[3];

    const float* base = features + ((size_t)b * CH + cg * CPW) * PLANE + xc;
    const float* q0 = base + yrow[0] * FW;
    const float* q1 = base + yrow[1] * FW;
    const float* q2 = base + yrow[2] * FW;
    const float* q3 = base + yrow[3] * FW;

    size_t     obase    = ((size_t)n * CH + (size_t)cg * CPW) * 49
                          + ph * POOLED + (lane >> 2);
    const bool do_store = ((lane & 3) == 0) && (lane < 4 * POOLED);

#pragma unroll
    for (int batch = 0; batch < CPW / CB; batch++) {
        float t0[CB], t1[CB], t2[CB], t3[CB];
        // Phase 1: issue all 4*CB loads back-to-back (high MLP).
#pragma unroll
        for (int c = 0; c < CB; c++) {
            const int off = (batch * CB + c) * PLANE;
            t0[c] = __ldg(q0 + off);
            t1[c] = __ldg(q1 + off);
            t2[c] = __ldg(q2 + off);
            t3[c] = __ldg(q3 + off);
        }
        // Phase 2: weight, reduce, store.
#pragma unroll
        for (int c = 0; c < CB; c++) {
            float v =      w0 * t0[c];
            v = fmaf(w1, t1[c], v);
            v = fmaf(w2, t2[c], v);
            v = fmaf(w3, t3[c], v);
            v += __shfl_xor_sync(0xffffffffu, v, 1);
            v += __shfl_xor_sync(0xffffffffu, v, 2);
            if (do_store) out[obase + (size_t)(batch * CB + c) * 49] = v;
        }
    }
}

extern "C" void kernel_launch(void* const* d_in, const int* in_sizes, int n_in,
                              void* d_out, int out_size)
{
    const float* features = (const float*)d_in[0];
    const float* rois     = (const float*)d_in[1];
    float*       out      = (float*)d_out;

    const int n_rois      = in_sizes[1] / 5;                 // 512
    const int total_warps = n_rois * NCG * POOLED;           // 57344
    const int wpb         = 8;                               // 256 threads
    const int blocks      = (total_warps + wpb - 1) / wpb;   // 7168

    roi_align_warp<<<blocks, wpb * 32>>>(features, rois, out);
}